// round 1
// baseline (speedup 1.0000x reference)
#include <cuda_runtime.h>
#include <stdint.h>

// Problem constants (match reference_code)
#define N_USERS 200000
#define N_ITEMS 100000
#define D       128           // feature dim; 32 lanes * float4

// ---------------- scratch (device globals; no runtime allocation) ----------
__device__ float g_y[(size_t)N_USERS * D];   // user-side intermediate, 102.4 MB
__device__ float g_udeg[N_USERS];
__device__ float g_ideg[N_ITEMS];

// ---------------- kernels ---------------------------------------------------

__global__ void zero_f4_kernel(float4* __restrict__ p, long long n4) {
    long long i = (long long)blockIdx.x * blockDim.x + threadIdx.x;
    if (i < n4) p[i] = make_float4(0.f, 0.f, 0.f, 0.f);
}

__global__ void degree_kernel(const float* __restrict__ vals,
                              const int* __restrict__ rows,
                              const int* __restrict__ cols,
                              int nnz) {
    int e = blockIdx.x * blockDim.x + threadIdx.x;
    if (e >= nnz) return;
    float v = vals[e];
    atomicAdd(&g_udeg[rows[e]], v);
    atomicAdd(&g_ideg[cols[e]], v);
}

// pass 1: y[rows[e], :] += nv_e * x[cols[e], :]
// one warp per edge; lane handles 4 consecutive floats
__global__ void spmm_pass1_kernel(const float* __restrict__ vals,
                                  const float* __restrict__ x,
                                  const int* __restrict__ rows,
                                  const int* __restrict__ cols,
                                  int nnz) {
    int gtid = blockIdx.x * blockDim.x + threadIdx.x;
    int e    = gtid >> 5;
    int lane = gtid & 31;
    if (e >= nnz) return;

    int r = rows[e];
    int c = cols[e];
    float nv = vals[e] * rsqrtf(fmaxf(g_udeg[r], 1.0f))
                       * rsqrtf(fmaxf(g_ideg[c], 1.0f));

    float4 xv = reinterpret_cast<const float4*>(x + (size_t)c * D)[lane];
    float* yr = g_y + (size_t)r * D + lane * 4;
    atomicAdd(yr + 0, nv * xv.x);
    atomicAdd(yr + 1, nv * xv.y);
    atomicAdd(yr + 2, nv * xv.z);
    atomicAdd(yr + 3, nv * xv.w);
}

// pass 2: out[cols[e], :] += nv_e * y[rows[e], :]   (out pre-zeroed)
__global__ void spmm_pass2_kernel(const float* __restrict__ vals,
                                  const int* __restrict__ rows,
                                  const int* __restrict__ cols,
                                  float* __restrict__ out,
                                  int nnz) {
    int gtid = blockIdx.x * blockDim.x + threadIdx.x;
    int e    = gtid >> 5;
    int lane = gtid & 31;
    if (e >= nnz) return;

    int r = rows[e];
    int c = cols[e];
    float nv = vals[e] * rsqrtf(fmaxf(g_udeg[r], 1.0f))
                       * rsqrtf(fmaxf(g_ideg[c], 1.0f));

    float4 yv = reinterpret_cast<const float4*>(g_y + (size_t)r * D)[lane];
    float* orow = out + (size_t)c * D + lane * 4;
    atomicAdd(orow + 0, nv * yv.x);
    atomicAdd(orow + 1, nv * yv.y);
    atomicAdd(orow + 2, nv * yv.z);
    atomicAdd(orow + 3, nv * yv.w);
}

// out = x - 2 * z   (z currently stored in out)
__global__ void finalize_kernel(const float4* __restrict__ x,
                                float4* __restrict__ out, long long n4) {
    long long i = (long long)blockIdx.x * blockDim.x + threadIdx.x;
    if (i >= n4) return;
    float4 xv = x[i];
    float4 zv = out[i];
    out[i] = make_float4(xv.x - 2.f * zv.x,
                         xv.y - 2.f * zv.y,
                         xv.z - 2.f * zv.z,
                         xv.w - 2.f * zv.w);
}

// ---------------- launch -----------------------------------------------------

extern "C" void kernel_launch(void* const* d_in, const int* in_sizes, int n_in,
                              void* d_out, int out_size) {
    const float* vals = (const float*)d_in[0];
    const float* x    = (const float*)d_in[1];
    const int*   rows = (const int*)d_in[2];
    const int*   cols = (const int*)d_in[3];
    float*       out  = (float*)d_out;

    const int nnz = in_sizes[0];

    // resolve device-global addresses (host-side, capture-safe)
    float* y_ptr;    cudaGetSymbolAddress((void**)&y_ptr,    g_y);
    float* udeg_ptr; cudaGetSymbolAddress((void**)&udeg_ptr, g_udeg);
    float* ideg_ptr; cudaGetSymbolAddress((void**)&ideg_ptr, g_ideg);

    const int T = 256;

    // 1. zero scratch + output
    {
        long long n4 = (long long)N_USERS * D / 4;
        zero_f4_kernel<<<(unsigned)((n4 + T - 1) / T), T>>>((float4*)y_ptr, n4);
    }
    {
        // degrees: N_USERS + N_ITEMS floats, both 4-float aligned counts
        long long n4u = N_USERS / 4, n4i = N_ITEMS / 4;
        zero_f4_kernel<<<(unsigned)((n4u + T - 1) / T), T>>>((float4*)udeg_ptr, n4u);
        zero_f4_kernel<<<(unsigned)((n4i + T - 1) / T), T>>>((float4*)ideg_ptr, n4i);
    }
    {
        long long n4 = (long long)out_size / 4;
        zero_f4_kernel<<<(unsigned)((n4 + T - 1) / T), T>>>((float4*)out, n4);
    }

    // 2. degrees
    degree_kernel<<<(nnz + T - 1) / T, T>>>(vals, rows, cols, nnz);

    // 3. SpMM pass 1: y = A_norm @ x   (scatter by user row)
    {
        long long threads = (long long)nnz * 32;
        spmm_pass1_kernel<<<(unsigned)((threads + T - 1) / T), T>>>(vals, x, rows, cols, nnz);
    }

    // 4. SpMM pass 2: z = A_norm^T @ y  (scatter by item col, into out)
    {
        long long threads = (long long)nnz * 32;
        spmm_pass2_kernel<<<(unsigned)((threads + T - 1) / T), T>>>(vals, rows, cols, out, nnz);
    }

    // 5. out = x - 2 * z
    {
        long long n4 = (long long)out_size / 4;
        finalize_kernel<<<(unsigned)((n4 + T - 1) / T), T>>>((const float4*)x, (float4*)out, n4);
    }
}

// round 2
// speedup vs baseline: 1.9764x; 1.9764x over previous
#include <cuda_runtime.h>
#include <stdint.h>

// Problem constants (match reference_code)
#define N_USERS 200000
#define N_ITEMS 100000
#define NNZ_CAP 5000000
#define D       128           // feature dim; 32 lanes * float4

// ---------------- scratch (device globals; no runtime allocation) ----------
__device__ float g_y[(size_t)N_USERS * D];   // user-side intermediate, 102.4 MB
__device__ float g_udeg[N_USERS];            // becomes u_dinv after rsqrt pass
__device__ float g_ideg[N_ITEMS];            // becomes i_dinv after rsqrt pass
__device__ float g_nv[NNZ_CAP];              // normalized edge values, 20 MB

// ---------------- helpers ----------------------------------------------------

__device__ __forceinline__ void red_add_v4(float* addr, float a, float b,
                                           float c, float d) {
    asm volatile("red.global.add.v4.f32 [%0], {%1, %2, %3, %4};"
                 :: "l"(addr), "f"(a), "f"(b), "f"(c), "f"(d)
                 : "memory");
}

// ---------------- kernels ---------------------------------------------------

__global__ void zero_f4_kernel(float4* __restrict__ p, long long n4) {
    long long i = (long long)blockIdx.x * blockDim.x + threadIdx.x;
    if (i < n4) p[i] = make_float4(0.f, 0.f, 0.f, 0.f);
}

__global__ void degree_kernel(const float* __restrict__ vals,
                              const int* __restrict__ rows,
                              const int* __restrict__ cols,
                              int nnz) {
    int e = blockIdx.x * blockDim.x + threadIdx.x;
    if (e >= nnz) return;
    float v = vals[e];
    atomicAdd(&g_udeg[rows[e]], v);
    atomicAdd(&g_ideg[cols[e]], v);
}

// deg -> clamp(deg,1)^-0.5 in place
__global__ void rsqrt_kernel(float* __restrict__ p, int n) {
    int i = blockIdx.x * blockDim.x + threadIdx.x;
    if (i < n) p[i] = rsqrtf(fmaxf(p[i], 1.0f));
}

// nv[e] = vals[e] * u_dinv[rows[e]] * i_dinv[cols[e]]
__global__ void normvals_kernel(const float* __restrict__ vals,
                                const int* __restrict__ rows,
                                const int* __restrict__ cols,
                                int nnz) {
    int e = blockIdx.x * blockDim.x + threadIdx.x;
    if (e >= nnz) return;
    g_nv[e] = vals[e] * g_udeg[rows[e]] * g_ideg[cols[e]];
}

// pass 1: y[rows[e], :] += nv_e * x[cols[e], :]
// one warp per edge; lane handles 4 consecutive floats, one v4 reduction
__global__ void spmm_pass1_kernel(const float* __restrict__ x,
                                  const int* __restrict__ rows,
                                  const int* __restrict__ cols,
                                  int nnz) {
    int gtid = blockIdx.x * blockDim.x + threadIdx.x;
    int e    = gtid >> 5;
    int lane = gtid & 31;
    if (e >= nnz) return;

    int   r  = __ldg(rows + e);
    int   c  = __ldg(cols + e);
    float nv = __ldg(g_nv + e);

    float4 xv = __ldg(reinterpret_cast<const float4*>(x + (size_t)c * D) + lane);
    float* yr = g_y + (size_t)r * D + lane * 4;
    red_add_v4(yr, nv * xv.x, nv * xv.y, nv * xv.z, nv * xv.w);
}

// pass 2: out[cols[e], :] += nv_e * y[rows[e], :]   (out pre-zeroed)
__global__ void spmm_pass2_kernel(const int* __restrict__ rows,
                                  const int* __restrict__ cols,
                                  float* __restrict__ out,
                                  int nnz) {
    int gtid = blockIdx.x * blockDim.x + threadIdx.x;
    int e    = gtid >> 5;
    int lane = gtid & 31;
    if (e >= nnz) return;

    int   r  = __ldg(rows + e);
    int   c  = __ldg(cols + e);
    float nv = __ldg(g_nv + e);

    float4 yv = __ldg(reinterpret_cast<const float4*>(g_y + (size_t)r * D) + lane);
    float* orow = out + (size_t)c * D + lane * 4;
    red_add_v4(orow, nv * yv.x, nv * yv.y, nv * yv.z, nv * yv.w);
}

// out = x - 2 * z   (z currently stored in out)
__global__ void finalize_kernel(const float4* __restrict__ x,
                                float4* __restrict__ out, long long n4) {
    long long i = (long long)blockIdx.x * blockDim.x + threadIdx.x;
    if (i >= n4) return;
    float4 xv = x[i];
    float4 zv = out[i];
    out[i] = make_float4(xv.x - 2.f * zv.x,
                         xv.y - 2.f * zv.y,
                         xv.z - 2.f * zv.z,
                         xv.w - 2.f * zv.w);
}

// ---------------- launch -----------------------------------------------------

extern "C" void kernel_launch(void* const* d_in, const int* in_sizes, int n_in,
                              void* d_out, int out_size) {
    const float* vals = (const float*)d_in[0];
    const float* x    = (const float*)d_in[1];
    const int*   rows = (const int*)d_in[2];
    const int*   cols = (const int*)d_in[3];
    float*       out  = (float*)d_out;

    const int nnz = in_sizes[0];

    // resolve device-global addresses (host-side, capture-safe)
    float* y_ptr;    cudaGetSymbolAddress((void**)&y_ptr,    g_y);
    float* udeg_ptr; cudaGetSymbolAddress((void**)&udeg_ptr, g_udeg);
    float* ideg_ptr; cudaGetSymbolAddress((void**)&ideg_ptr, g_ideg);

    const int T = 256;

    // 1. zero scratch + output
    {
        long long n4 = (long long)N_USERS * D / 4;
        zero_f4_kernel<<<(unsigned)((n4 + T - 1) / T), T>>>((float4*)y_ptr, n4);
    }
    {
        long long n4u = N_USERS / 4, n4i = N_ITEMS / 4;
        zero_f4_kernel<<<(unsigned)((n4u + T - 1) / T), T>>>((float4*)udeg_ptr, n4u);
        zero_f4_kernel<<<(unsigned)((n4i + T - 1) / T), T>>>((float4*)ideg_ptr, n4i);
    }
    {
        long long n4 = (long long)out_size / 4;
        zero_f4_kernel<<<(unsigned)((n4 + T - 1) / T), T>>>((float4*)out, n4);
    }

    // 2. degrees, then deg -> dinv in place
    degree_kernel<<<(nnz + T - 1) / T, T>>>(vals, rows, cols, nnz);
    rsqrt_kernel<<<(N_USERS + T - 1) / T, T>>>(udeg_ptr, N_USERS);
    rsqrt_kernel<<<(N_ITEMS + T - 1) / T, T>>>(ideg_ptr, N_ITEMS);

    // 3. normalized edge values (one pass, reused by both SpMMs)
    normvals_kernel<<<(nnz + T - 1) / T, T>>>(vals, rows, cols, nnz);

    // 4. SpMM pass 1: y = A_norm @ x   (scatter by user row)
    {
        long long threads = (long long)nnz * 32;
        spmm_pass1_kernel<<<(unsigned)((threads + T - 1) / T), T>>>(x, rows, cols, nnz);
    }

    // 5. SpMM pass 2: z = A_norm^T @ y  (scatter by item col, into out)
    {
        long long threads = (long long)nnz * 32;
        spmm_pass2_kernel<<<(unsigned)((threads + T - 1) / T), T>>>(rows, cols, out, nnz);
    }

    // 6. out = x - 2 * z
    {
        long long n4 = (long long)out_size / 4;
        finalize_kernel<<<(unsigned)((n4 + T - 1) / T), T>>>((const float4*)x, (float4*)out, n4);
    }
}

// round 3
// speedup vs baseline: 4.3256x; 2.1886x over previous
#include <cuda_runtime.h>
#include <stdint.h>

// Problem constants (match reference_code)
#define N_USERS 200000
#define N_ITEMS 100000
#define N_BOTH  (N_USERS + N_ITEMS)
#define NNZ_CAP 5000000
#define D       128           // feature dim; 32 lanes * float4
#define SCAN_B  1024

// ---------------- scratch (device globals; no runtime allocation) ----------
__device__ float g_y[(size_t)N_USERS * D];       // user-side intermediate, 102.4 MB
__device__ float g_deg[N_BOTH];                  // [users | items]; becomes dinv
__device__ int   g_cnt[N_BOTH];                  // per-node edge counts
__device__ int   g_off[N_BOTH];                  // exclusive-scan offsets (pristine)
__device__ int   g_cur[N_BOTH];                  // working cursors for scatter
__device__ int   g_bsums[SCAN_B];                // scan block sums scratch
__device__ int2  g_uedges[NNZ_CAP];              // CSR by user: (col, nv bits)
__device__ int2  g_iedges[NNZ_CAP];              // CSC by item: (row, nv bits)

// ---------------- kernels ---------------------------------------------------

__global__ void zero_i4_kernel(int4* __restrict__ p, int n4) {
    int i = blockIdx.x * blockDim.x + threadIdx.x;
    if (i < n4) p[i] = make_int4(0, 0, 0, 0);
}

// degrees (float) + histogram counts (int), both L2-resident small arrays
__global__ void deg_hist_kernel(const float* __restrict__ vals,
                                const int* __restrict__ rows,
                                const int* __restrict__ cols,
                                int nnz) {
    int e = blockIdx.x * blockDim.x + threadIdx.x;
    if (e >= nnz) return;
    float v = vals[e];
    int r = rows[e];
    int c = cols[e] + N_USERS;
    atomicAdd(&g_deg[r], v);
    atomicAdd(&g_deg[c], v);
    atomicAdd(&g_cnt[r], 1);
    atomicAdd(&g_cnt[c], 1);
}

// deg -> clamp(deg,1)^-0.5 in place
__global__ void rsqrt_kernel(int n) {
    int i = blockIdx.x * blockDim.x + threadIdx.x;
    if (i < n) g_deg[i] = rsqrtf(fmaxf(g_deg[i], 1.0f));
}

// ---- exclusive scan (3 kernels), n <= SCAN_B * SCAN_B ----
__global__ void scan_block_kernel(const int* __restrict__ in, int* __restrict__ out,
                                  int* __restrict__ bsums, int n) {
    __shared__ int sh[SCAN_B];
    int i = blockIdx.x * SCAN_B + threadIdx.x;
    int v = (i < n) ? in[i] : 0;
    sh[threadIdx.x] = v;
    __syncthreads();
    #pragma unroll
    for (int off = 1; off < SCAN_B; off <<= 1) {
        int t = (threadIdx.x >= (unsigned)off) ? sh[threadIdx.x - off] : 0;
        __syncthreads();
        sh[threadIdx.x] += t;
        __syncthreads();
    }
    if (i < n) out[i] = sh[threadIdx.x] - v;          // exclusive
    if (threadIdx.x == SCAN_B - 1) bsums[blockIdx.x] = sh[SCAN_B - 1];
}

__global__ void scan_sums_kernel(int* __restrict__ bsums, int nb) {
    __shared__ int sh[SCAN_B];
    int v = (threadIdx.x < (unsigned)nb) ? bsums[threadIdx.x] : 0;
    sh[threadIdx.x] = v;
    __syncthreads();
    #pragma unroll
    for (int off = 1; off < SCAN_B; off <<= 1) {
        int t = (threadIdx.x >= (unsigned)off) ? sh[threadIdx.x - off] : 0;
        __syncthreads();
        sh[threadIdx.x] += t;
        __syncthreads();
    }
    if (threadIdx.x < (unsigned)nb) bsums[threadIdx.x] = sh[threadIdx.x] - v;  // exclusive
}

__global__ void scan_add_kernel(int* __restrict__ off_, int* __restrict__ cur,
                                const int* __restrict__ bsums, int n) {
    int i = blockIdx.x * SCAN_B + threadIdx.x;
    if (i < n) {
        int o = off_[i] + bsums[blockIdx.x];
        off_[i] = o;
        cur[i] = o;
    }
}

// scatter edges into CSR (by user) and CSC (by item), with fused normalization
__global__ void build_kernel(const float* __restrict__ vals,
                             const int* __restrict__ rows,
                             const int* __restrict__ cols,
                             int nnz) {
    int e = blockIdx.x * blockDim.x + threadIdx.x;
    if (e >= nnz) return;
    int r = rows[e];
    int c = cols[e];
    float nv = vals[e] * g_deg[r] * g_deg[c + N_USERS];
    int nvb = __float_as_int(nv);
    int pu = atomicAdd(&g_cur[r], 1);
    g_uedges[pu] = make_int2(c, nvb);
    int pi = atomicAdd(&g_cur[c + N_USERS], 1);
    g_iedges[pi] = make_int2(r, nvb);
}

// pass 1: y[u, :] = sum_{e in row u} nv_e * x[col_e, :]
// one warp per user row; coalesced edge loads + shuffle broadcast
__global__ void spmm1_kernel(const float* __restrict__ x, int nrows) {
    int w    = (blockIdx.x * blockDim.x + threadIdx.x) >> 5;
    int lane = threadIdx.x & 31;
    if (w >= nrows) return;

    int s   = g_off[w];
    int end = s + g_cnt[w];

    float4 acc = make_float4(0.f, 0.f, 0.f, 0.f);
    for (int base = s; base < end; base += 32) {
        int j = base + lane;
        int2 er = make_int2(0, 0);
        if (j < end) er = __ldg(&g_uedges[j]);
        int m = min(32, end - base);
        for (int k = 0; k < m; k++) {
            int   cc = __shfl_sync(0xffffffffu, er.x, k);
            float vv = __int_as_float(__shfl_sync(0xffffffffu, er.y, k));
            float4 xv = __ldg(reinterpret_cast<const float4*>(x + (size_t)cc * D) + lane);
            acc.x += vv * xv.x;
            acc.y += vv * xv.y;
            acc.z += vv * xv.z;
            acc.w += vv * xv.w;
        }
    }
    reinterpret_cast<float4*>(g_y + (size_t)w * D)[lane] = acc;
}

// pass 2 + finalize: out[i, :] = x[i, :] - 2 * sum_{e in col i} nv_e * y[row_e, :]
__global__ void spmm2_kernel(const float* __restrict__ x,
                             float* __restrict__ out, int nrows) {
    int w    = (blockIdx.x * blockDim.x + threadIdx.x) >> 5;
    int lane = threadIdx.x & 31;
    if (w >= nrows) return;

    int s   = g_off[w + N_USERS];
    int end = s + g_cnt[w + N_USERS];

    float4 acc = make_float4(0.f, 0.f, 0.f, 0.f);
    for (int base = s; base < end; base += 32) {
        int j = base + lane;
        int2 er = make_int2(0, 0);
        if (j < end) er = __ldg(&g_iedges[j]);
        int m = min(32, end - base);
        for (int k = 0; k < m; k++) {
            int   rr = __shfl_sync(0xffffffffu, er.x, k);
            float vv = __int_as_float(__shfl_sync(0xffffffffu, er.y, k));
            float4 yv = __ldg(reinterpret_cast<const float4*>(g_y + (size_t)rr * D) + lane);
            acc.x += vv * yv.x;
            acc.y += vv * yv.y;
            acc.z += vv * yv.z;
            acc.w += vv * yv.w;
        }
    }
    float4 xv = __ldg(reinterpret_cast<const float4*>(x + (size_t)w * D) + lane);
    reinterpret_cast<float4*>(out + (size_t)w * D)[lane] =
        make_float4(xv.x - 2.f * acc.x, xv.y - 2.f * acc.y,
                    xv.z - 2.f * acc.z, xv.w - 2.f * acc.w);
}

// ---------------- launch -----------------------------------------------------

extern "C" void kernel_launch(void* const* d_in, const int* in_sizes, int n_in,
                              void* d_out, int out_size) {
    const float* vals = (const float*)d_in[0];
    const float* x    = (const float*)d_in[1];
    const int*   rows = (const int*)d_in[2];
    const int*   cols = (const int*)d_in[3];
    float*       out  = (float*)d_out;

    const int nnz = in_sizes[0];

    float* deg_ptr;  cudaGetSymbolAddress((void**)&deg_ptr,  g_deg);
    int*   cnt_ptr;  cudaGetSymbolAddress((void**)&cnt_ptr,  g_cnt);
    int*   off_ptr;  cudaGetSymbolAddress((void**)&off_ptr,  g_off);
    int*   cur_ptr;  cudaGetSymbolAddress((void**)&cur_ptr,  g_cur);
    int*   bs_ptr;   cudaGetSymbolAddress((void**)&bs_ptr,   g_bsums);

    const int T = 256;

    // 1. zero degrees + counts (small, L2-resident)
    zero_i4_kernel<<<(N_BOTH / 4 + T - 1) / T, T>>>((int4*)deg_ptr, N_BOTH / 4);
    zero_i4_kernel<<<(N_BOTH / 4 + T - 1) / T, T>>>((int4*)cnt_ptr, N_BOTH / 4);

    // 2. degrees + histogram, then deg -> dinv in place
    deg_hist_kernel<<<(nnz + T - 1) / T, T>>>(vals, rows, cols, nnz);
    rsqrt_kernel<<<(N_BOTH + T - 1) / T, T>>>(N_BOTH);

    // 3. exclusive scans: user section, then item section
    {
        int nbU = (N_USERS + SCAN_B - 1) / SCAN_B;
        scan_block_kernel<<<nbU, SCAN_B>>>(cnt_ptr, off_ptr, bs_ptr, N_USERS);
        scan_sums_kernel<<<1, SCAN_B>>>(bs_ptr, nbU);
        scan_add_kernel<<<nbU, SCAN_B>>>(off_ptr, cur_ptr, bs_ptr, N_USERS);
    }
    {
        int nbI = (N_ITEMS + SCAN_B - 1) / SCAN_B;
        scan_block_kernel<<<nbI, SCAN_B>>>(cnt_ptr + N_USERS, off_ptr + N_USERS,
                                           bs_ptr, N_ITEMS);
        scan_sums_kernel<<<1, SCAN_B>>>(bs_ptr, nbI);
        scan_add_kernel<<<nbI, SCAN_B>>>(off_ptr + N_USERS, cur_ptr + N_USERS,
                                         bs_ptr, N_ITEMS);
    }

    // 4. scatter edges into CSR + CSC with fused normalization
    build_kernel<<<(nnz + T - 1) / T, T>>>(vals, rows, cols, nnz);

    // 5. SpMM pass 1: y = A_norm @ x   (gather per user row, no atomics)
    {
        long long threads = (long long)N_USERS * 32;
        spmm1_kernel<<<(unsigned)((threads + T - 1) / T), T>>>(x, N_USERS);
    }

    // 6. SpMM pass 2 + finalize: out = x - 2 * (A_norm^T @ y)
    {
        long long threads = (long long)N_ITEMS * 32;
        spmm2_kernel<<<(unsigned)((threads + T - 1) / T), T>>>(x, out, N_ITEMS);
    }
}

// round 4
// speedup vs baseline: 5.6591x; 1.3083x over previous
#include <cuda_runtime.h>
#include <cuda_fp16.h>
#include <stdint.h>

// Problem constants (match reference_code)
#define N_USERS 200000
#define N_ITEMS 100000
#define N_BOTH  (N_USERS + N_ITEMS)
#define NNZ_CAP 5000000
#define D       128           // feature dim; 32 lanes * 4 elems
#define SCAN_B  1024

// ---------------- scratch (device globals; no runtime allocation) ----------
__device__ __half g_yh[(size_t)N_USERS * D];     // fp16 intermediate, 51.2 MB
__device__ __half g_xh[(size_t)N_ITEMS * D];     // fp16 copy of x, 25.6 MB
__device__ float  g_deg[N_BOTH];                 // [users | items]; becomes dinv
__device__ int    g_cnt[N_BOTH];                 // per-node edge counts
__device__ int    g_off[N_BOTH];                 // exclusive-scan offsets (pristine)
__device__ int    g_cur[N_BOTH];                 // working cursors for scatter
__device__ int    g_bsums[SCAN_B];               // scan block sums scratch
__device__ int2   g_uedges[NNZ_CAP];             // CSR by user: (col, nv bits)
__device__ int2   g_iedges[NNZ_CAP];             // CSC by item: (row, nv bits)

// ---------------- kernels ---------------------------------------------------

__global__ void zero_i4_kernel(int4* __restrict__ p, int n4) {
    int i = blockIdx.x * blockDim.x + threadIdx.x;
    if (i < n4) p[i] = make_int4(0, 0, 0, 0);
}

// degrees (float) + histogram counts (int), both L2-resident small arrays
__global__ void deg_hist_kernel(const float* __restrict__ vals,
                                const int* __restrict__ rows,
                                const int* __restrict__ cols,
                                int nnz) {
    int e = blockIdx.x * blockDim.x + threadIdx.x;
    if (e >= nnz) return;
    float v = vals[e];
    int r = rows[e];
    int c = cols[e] + N_USERS;
    atomicAdd(&g_deg[r], v);
    atomicAdd(&g_deg[c], v);
    atomicAdd(&g_cnt[r], 1);
    atomicAdd(&g_cnt[c], 1);
}

// deg -> clamp(deg,1)^-0.5 in place
__global__ void rsqrt_kernel(int n) {
    int i = blockIdx.x * blockDim.x + threadIdx.x;
    if (i < n) g_deg[i] = rsqrtf(fmaxf(g_deg[i], 1.0f));
}

// x (f32) -> g_xh (fp16), streaming
__global__ void cvt_x_kernel(const float4* __restrict__ x, int n4) {
    int i = blockIdx.x * blockDim.x + threadIdx.x;
    if (i >= n4) return;
    float4 v = x[i];
    __half2 h0 = __floats2half2_rn(v.x, v.y);
    __half2 h1 = __floats2half2_rn(v.z, v.w);
    reinterpret_cast<uint2*>(g_xh)[i] =
        make_uint2(*(unsigned*)&h0, *(unsigned*)&h1);
}

// ---- exclusive scan (3 kernels), n <= SCAN_B * SCAN_B ----
__global__ void scan_block_kernel(const int* __restrict__ in, int* __restrict__ out,
                                  int* __restrict__ bsums, int n) {
    __shared__ int sh[SCAN_B];
    int i = blockIdx.x * SCAN_B + threadIdx.x;
    int v = (i < n) ? in[i] : 0;
    sh[threadIdx.x] = v;
    __syncthreads();
    #pragma unroll
    for (int off = 1; off < SCAN_B; off <<= 1) {
        int t = (threadIdx.x >= (unsigned)off) ? sh[threadIdx.x - off] : 0;
        __syncthreads();
        sh[threadIdx.x] += t;
        __syncthreads();
    }
    if (i < n) out[i] = sh[threadIdx.x] - v;          // exclusive
    if (threadIdx.x == SCAN_B - 1) bsums[blockIdx.x] = sh[SCAN_B - 1];
}

__global__ void scan_sums_kernel(int* __restrict__ bsums, int nb) {
    __shared__ int sh[SCAN_B];
    int v = (threadIdx.x < (unsigned)nb) ? bsums[threadIdx.x] : 0;
    sh[threadIdx.x] = v;
    __syncthreads();
    #pragma unroll
    for (int off = 1; off < SCAN_B; off <<= 1) {
        int t = (threadIdx.x >= (unsigned)off) ? sh[threadIdx.x - off] : 0;
        __syncthreads();
        sh[threadIdx.x] += t;
        __syncthreads();
    }
    if (threadIdx.x < (unsigned)nb) bsums[threadIdx.x] = sh[threadIdx.x] - v;  // exclusive
}

__global__ void scan_add_kernel(int* __restrict__ off_, int* __restrict__ cur,
                                const int* __restrict__ bsums, int n) {
    int i = blockIdx.x * SCAN_B + threadIdx.x;
    if (i < n) {
        int o = off_[i] + bsums[blockIdx.x];
        off_[i] = o;
        cur[i] = o;
    }
}

// scatter edges into CSR (by user) and CSC (by item), with fused normalization
__global__ void build_kernel(const float* __restrict__ vals,
                             const int* __restrict__ rows,
                             const int* __restrict__ cols,
                             int nnz) {
    int e = blockIdx.x * blockDim.x + threadIdx.x;
    if (e >= nnz) return;
    int r = rows[e];
    int c = cols[e];
    float nv = vals[e] * g_deg[r] * g_deg[c + N_USERS];
    int nvb = __float_as_int(nv);
    int pu = atomicAdd(&g_cur[r], 1);
    g_uedges[pu] = make_int2(c, nvb);
    int pi = atomicAdd(&g_cur[c + N_USERS], 1);
    g_iedges[pi] = make_int2(r, nvb);
}

__device__ __forceinline__ float4 half4_to_float4(uint2 u) {
    __half2 h0 = *(__half2*)&u.x;
    __half2 h1 = *(__half2*)&u.y;
    float2 f0 = __half22float2(h0);
    float2 f1 = __half22float2(h1);
    return make_float4(f0.x, f0.y, f1.x, f1.y);
}

// pass 1: y[u, :] = sum_{e in row u} nv_e * x_h[col_e, :]   (fp16 gather, fp32 acc)
__global__ void spmm1_kernel(int nrows) {
    int w    = (blockIdx.x * blockDim.x + threadIdx.x) >> 5;
    int lane = threadIdx.x & 31;
    if (w >= nrows) return;

    int s   = g_off[w];
    int end = s + g_cnt[w];

    float4 acc = make_float4(0.f, 0.f, 0.f, 0.f);
    for (int base = s; base < end; base += 32) {
        int j = base + lane;
        int2 er = make_int2(0, 0);
        if (j < end) er = __ldg(&g_uedges[j]);
        int m = min(32, end - base);
        for (int k = 0; k < m; k++) {
            int   cc = __shfl_sync(0xffffffffu, er.x, k);
            float vv = __int_as_float(__shfl_sync(0xffffffffu, er.y, k));
            uint2 u = __ldg(reinterpret_cast<const uint2*>(g_xh + (size_t)cc * D) + lane);
            float4 xv = half4_to_float4(u);
            acc.x += vv * xv.x;
            acc.y += vv * xv.y;
            acc.z += vv * xv.z;
            acc.w += vv * xv.w;
        }
    }
    __half2 h0 = __floats2half2_rn(acc.x, acc.y);
    __half2 h1 = __floats2half2_rn(acc.z, acc.w);
    reinterpret_cast<uint2*>(g_yh + (size_t)w * D)[lane] =
        make_uint2(*(unsigned*)&h0, *(unsigned*)&h1);
}

// pass 2 + finalize: out[i, :] = x[i, :] - 2 * sum_{e in col i} nv_e * y_h[row_e, :]
__global__ void spmm2_kernel(const float* __restrict__ x,
                             float* __restrict__ out, int nrows) {
    int w    = (blockIdx.x * blockDim.x + threadIdx.x) >> 5;
    int lane = threadIdx.x & 31;
    if (w >= nrows) return;

    int s   = g_off[w + N_USERS];
    int end = s + g_cnt[w + N_USERS];

    float4 acc = make_float4(0.f, 0.f, 0.f, 0.f);
    for (int base = s; base < end; base += 32) {
        int j = base + lane;
        int2 er = make_int2(0, 0);
        if (j < end) er = __ldg(&g_iedges[j]);
        int m = min(32, end - base);
        for (int k = 0; k < m; k++) {
            int   rr = __shfl_sync(0xffffffffu, er.x, k);
            float vv = __int_as_float(__shfl_sync(0xffffffffu, er.y, k));
            uint2 u = __ldg(reinterpret_cast<const uint2*>(g_yh + (size_t)rr * D) + lane);
            float4 yv = half4_to_float4(u);
            acc.x += vv * yv.x;
            acc.y += vv * yv.y;
            acc.z += vv * yv.z;
            acc.w += vv * yv.w;
        }
    }
    float4 xv = __ldg(reinterpret_cast<const float4*>(x + (size_t)w * D) + lane);
    reinterpret_cast<float4*>(out + (size_t)w * D)[lane] =
        make_float4(xv.x - 2.f * acc.x, xv.y - 2.f * acc.y,
                    xv.z - 2.f * acc.z, xv.w - 2.f * acc.w);
}

// ---------------- launch -----------------------------------------------------

extern "C" void kernel_launch(void* const* d_in, const int* in_sizes, int n_in,
                              void* d_out, int out_size) {
    const float* vals = (const float*)d_in[0];
    const float* x    = (const float*)d_in[1];
    const int*   rows = (const int*)d_in[2];
    const int*   cols = (const int*)d_in[3];
    float*       out  = (float*)d_out;

    const int nnz = in_sizes[0];

    float* deg_ptr;  cudaGetSymbolAddress((void**)&deg_ptr,  g_deg);
    int*   cnt_ptr;  cudaGetSymbolAddress((void**)&cnt_ptr,  g_cnt);
    int*   off_ptr;  cudaGetSymbolAddress((void**)&off_ptr,  g_off);
    int*   cur_ptr;  cudaGetSymbolAddress((void**)&cur_ptr,  g_cur);
    int*   bs_ptr;   cudaGetSymbolAddress((void**)&bs_ptr,   g_bsums);

    const int T = 256;

    // 1. zero degrees + counts (small, L2-resident)
    zero_i4_kernel<<<(N_BOTH / 4 + T - 1) / T, T>>>((int4*)deg_ptr, N_BOTH / 4);
    zero_i4_kernel<<<(N_BOTH / 4 + T - 1) / T, T>>>((int4*)cnt_ptr, N_BOTH / 4);

    // 2. degrees + histogram; x -> fp16 copy; then deg -> dinv in place
    deg_hist_kernel<<<(nnz + T - 1) / T, T>>>(vals, rows, cols, nnz);
    {
        int n4 = N_ITEMS * D / 4;
        cvt_x_kernel<<<(n4 + T - 1) / T, T>>>((const float4*)x, n4);
    }
    rsqrt_kernel<<<(N_BOTH + T - 1) / T, T>>>(N_BOTH);

    // 3. exclusive scans: user section, then item section
    {
        int nbU = (N_USERS + SCAN_B - 1) / SCAN_B;
        scan_block_kernel<<<nbU, SCAN_B>>>(cnt_ptr, off_ptr, bs_ptr, N_USERS);
        scan_sums_kernel<<<1, SCAN_B>>>(bs_ptr, nbU);
        scan_add_kernel<<<nbU, SCAN_B>>>(off_ptr, cur_ptr, bs_ptr, N_USERS);
    }
    {
        int nbI = (N_ITEMS + SCAN_B - 1) / SCAN_B;
        scan_block_kernel<<<nbI, SCAN_B>>>(cnt_ptr + N_USERS, off_ptr + N_USERS,
                                           bs_ptr, N_ITEMS);
        scan_sums_kernel<<<1, SCAN_B>>>(bs_ptr, nbI);
        scan_add_kernel<<<nbI, SCAN_B>>>(off_ptr + N_USERS, cur_ptr + N_USERS,
                                         bs_ptr, N_ITEMS);
    }

    // 4. scatter edges into CSR + CSC with fused normalization
    build_kernel<<<(nnz + T - 1) / T, T>>>(vals, rows, cols, nnz);

    // 5. SpMM pass 1: y = A_norm @ x   (fp16 gather, no atomics)
    {
        long long threads = (long long)N_USERS * 32;
        spmm1_kernel<<<(unsigned)((threads + T - 1) / T), T>>>(N_USERS);
    }

    // 6. SpMM pass 2 + finalize: out = x - 2 * (A_norm^T @ y)
    {
        long long threads = (long long)N_ITEMS * 32;
        spmm2_kernel<<<(unsigned)((threads + T - 1) / T), T>>>(x, out, N_ITEMS);
    }
}

// round 5
// speedup vs baseline: 5.8255x; 1.0294x over previous
#include <cuda_runtime.h>
#include <cuda_fp16.h>
#include <stdint.h>

// Problem constants (match reference_code)
#define N_USERS 200000
#define N_ITEMS 100000
#define N_BOTH  (N_USERS + N_ITEMS)
#define NNZ_CAP 5000000
#define D       128           // feature dim
#define SCAN_B  1024

// ---------------- scratch (device globals; no runtime allocation) ----------
__device__ __half g_yh[(size_t)N_USERS * D];     // fp16 intermediate, 51.2 MB
__device__ __half g_xh[(size_t)N_ITEMS * D];     // fp16 copy of x, 25.6 MB
__device__ float2 g_degcnt[N_BOTH];              // (deg, count) per node
__device__ float  g_dinv[N_BOTH];                // clamp(deg,1)^-0.5
__device__ int    g_cntI[N_BOTH];                // integer counts (from degcnt.y)
__device__ int    g_off[N_BOTH];                 // exclusive-scan offsets (pristine)
__device__ int    g_cur[N_BOTH];                 // working cursors for scatter
__device__ int    g_bsums[SCAN_B];               // scan block sums scratch
__device__ int2   g_uedges[NNZ_CAP];             // CSR by user: (col, nv bits)
__device__ int2   g_iedges[NNZ_CAP];             // CSC by item: (row, nv bits)

// ---------------- helpers ----------------------------------------------------

__device__ __forceinline__ void red_add_v2(float2* addr, float a, float b) {
    asm volatile("red.global.add.v2.f32 [%0], {%1, %2};"
                 :: "l"(addr), "f"(a), "f"(b) : "memory");
}

// ---------------- kernels ---------------------------------------------------

__global__ void zero_i4_kernel(int4* __restrict__ p, int n4) {
    int i = blockIdx.x * blockDim.x + threadIdx.x;
    if (i < n4) p[i] = make_int4(0, 0, 0, 0);
}

// fused degree-sum + count histogram: one v2 reduction per endpoint
__global__ void deg_hist_kernel(const float* __restrict__ vals,
                                const int* __restrict__ rows,
                                const int* __restrict__ cols,
                                int nnz) {
    int e = blockIdx.x * blockDim.x + threadIdx.x;
    if (e >= nnz) return;
    float v = vals[e];
    red_add_v2(&g_degcnt[rows[e]], v, 1.0f);
    red_add_v2(&g_degcnt[cols[e] + N_USERS], v, 1.0f);
}

// degcnt -> (dinv, int count)
__global__ void prep_kernel(int n) {
    int i = blockIdx.x * blockDim.x + threadIdx.x;
    if (i >= n) return;
    float2 dc = g_degcnt[i];
    g_dinv[i] = rsqrtf(fmaxf(dc.x, 1.0f));
    g_cntI[i] = (int)dc.y;
}

// x (f32) -> g_xh (fp16), streaming
__global__ void cvt_x_kernel(const float4* __restrict__ x, int n4) {
    int i = blockIdx.x * blockDim.x + threadIdx.x;
    if (i >= n4) return;
    float4 v = x[i];
    __half2 h0 = __floats2half2_rn(v.x, v.y);
    __half2 h1 = __floats2half2_rn(v.z, v.w);
    reinterpret_cast<uint2*>(g_xh)[i] =
        make_uint2(*(unsigned*)&h0, *(unsigned*)&h1);
}

// ---- exclusive scan (3 kernels), n <= SCAN_B * SCAN_B ----
__global__ void scan_block_kernel(const int* __restrict__ in, int* __restrict__ out,
                                  int* __restrict__ bsums, int n) {
    __shared__ int sh[SCAN_B];
    int i = blockIdx.x * SCAN_B + threadIdx.x;
    int v = (i < n) ? in[i] : 0;
    sh[threadIdx.x] = v;
    __syncthreads();
    #pragma unroll
    for (int off = 1; off < SCAN_B; off <<= 1) {
        int t = (threadIdx.x >= (unsigned)off) ? sh[threadIdx.x - off] : 0;
        __syncthreads();
        sh[threadIdx.x] += t;
        __syncthreads();
    }
    if (i < n) out[i] = sh[threadIdx.x] - v;          // exclusive
    if (threadIdx.x == SCAN_B - 1) bsums[blockIdx.x] = sh[SCAN_B - 1];
}

__global__ void scan_sums_kernel(int* __restrict__ bsums, int nb) {
    __shared__ int sh[SCAN_B];
    int v = (threadIdx.x < (unsigned)nb) ? bsums[threadIdx.x] : 0;
    sh[threadIdx.x] = v;
    __syncthreads();
    #pragma unroll
    for (int off = 1; off < SCAN_B; off <<= 1) {
        int t = (threadIdx.x >= (unsigned)off) ? sh[threadIdx.x - off] : 0;
        __syncthreads();
        sh[threadIdx.x] += t;
        __syncthreads();
    }
    if (threadIdx.x < (unsigned)nb) bsums[threadIdx.x] = sh[threadIdx.x] - v;  // exclusive
}

__global__ void scan_add_kernel(int* __restrict__ off_, int* __restrict__ cur,
                                const int* __restrict__ bsums, int n) {
    int i = blockIdx.x * SCAN_B + threadIdx.x;
    if (i < n) {
        int o = off_[i] + bsums[blockIdx.x];
        off_[i] = o;
        cur[i] = o;
    }
}

// scatter edges into CSR (by user) and CSC (by item), with fused normalization
__global__ void build_kernel(const float* __restrict__ vals,
                             const int* __restrict__ rows,
                             const int* __restrict__ cols,
                             int nnz) {
    int e = blockIdx.x * blockDim.x + threadIdx.x;
    if (e >= nnz) return;
    int r = rows[e];
    int c = cols[e];
    float nv = vals[e] * g_dinv[r] * g_dinv[c + N_USERS];
    int nvb = __float_as_int(nv);
    int pu = atomicAdd(&g_cur[r], 1);
    g_uedges[pu] = make_int2(c, nvb);
    int pi = atomicAdd(&g_cur[c + N_USERS], 1);
    g_iedges[pi] = make_int2(r, nvb);
}

// pass 1: y[u, :] = sum_{e in row u} nv_e * x_h[col_e, :]
// one warp per user row; 2 edges per iteration, 16 lanes x uint4 per edge
__global__ void spmm1_kernel(int nrows) {
    int w    = (blockIdx.x * blockDim.x + threadIdx.x) >> 5;
    int lane = threadIdx.x & 31;
    if (w >= nrows) return;
    int half = lane >> 4;
    int sub  = lane & 15;

    int s   = g_off[w];
    int end = s + g_cntI[w];

    float acc[8];
    #pragma unroll
    for (int i = 0; i < 8; i++) acc[i] = 0.f;

    for (int base = s; base < end; base += 32) {
        int j = base + lane;
        int2 er = make_int2(0, 0);
        if (j < end) er = __ldg(&g_uedges[j]);
        int m = min(32, end - base);
        int pairs = (m + 1) >> 1;
        for (int p = 0; p < pairs; p++) {
            int eidx = (p << 1) + half;
            int   cc = __shfl_sync(0xffffffffu, er.x, eidx);
            float vv = __int_as_float(__shfl_sync(0xffffffffu, er.y, eidx));
            if (eidx < m) {
                uint4 u = __ldg(reinterpret_cast<const uint4*>(g_xh + (size_t)cc * D) + sub);
                __half2 h0 = *(__half2*)&u.x, h1 = *(__half2*)&u.y;
                __half2 h2 = *(__half2*)&u.z, h3 = *(__half2*)&u.w;
                float2 f0 = __half22float2(h0), f1 = __half22float2(h1);
                float2 f2 = __half22float2(h2), f3 = __half22float2(h3);
                acc[0] += vv * f0.x; acc[1] += vv * f0.y;
                acc[2] += vv * f1.x; acc[3] += vv * f1.y;
                acc[4] += vv * f2.x; acc[5] += vv * f2.y;
                acc[6] += vv * f3.x; acc[7] += vv * f3.y;
            }
        }
    }
    // combine the two half-warp partial sums (same columns, disjoint edges)
    #pragma unroll
    for (int i = 0; i < 8; i++) acc[i] += __shfl_xor_sync(0xffffffffu, acc[i], 16);

    if (half == 0) {
        __half2 o0 = __floats2half2_rn(acc[0], acc[1]);
        __half2 o1 = __floats2half2_rn(acc[2], acc[3]);
        __half2 o2 = __floats2half2_rn(acc[4], acc[5]);
        __half2 o3 = __floats2half2_rn(acc[6], acc[7]);
        reinterpret_cast<uint4*>(g_yh + (size_t)w * D)[sub] =
            make_uint4(*(unsigned*)&o0, *(unsigned*)&o1,
                       *(unsigned*)&o2, *(unsigned*)&o3);
    }
}

// pass 2 + finalize: out[i, :] = x[i, :] - 2 * sum_{e in col i} nv_e * y_h[row_e, :]
__global__ void spmm2_kernel(const float* __restrict__ x,
                             float* __restrict__ out, int nrows) {
    int w    = (blockIdx.x * blockDim.x + threadIdx.x) >> 5;
    int lane = threadIdx.x & 31;
    if (w >= nrows) return;
    int half = lane >> 4;
    int sub  = lane & 15;

    int s   = g_off[w + N_USERS];
    int end = s + g_cntI[w + N_USERS];

    float acc[8];
    #pragma unroll
    for (int i = 0; i < 8; i++) acc[i] = 0.f;

    for (int base = s; base < end; base += 32) {
        int j = base + lane;
        int2 er = make_int2(0, 0);
        if (j < end) er = __ldg(&g_iedges[j]);
        int m = min(32, end - base);
        int pairs = (m + 1) >> 1;
        for (int p = 0; p < pairs; p++) {
            int eidx = (p << 1) + half;
            int   rr = __shfl_sync(0xffffffffu, er.x, eidx);
            float vv = __int_as_float(__shfl_sync(0xffffffffu, er.y, eidx));
            if (eidx < m) {
                uint4 u = __ldg(reinterpret_cast<const uint4*>(g_yh + (size_t)rr * D) + sub);
                __half2 h0 = *(__half2*)&u.x, h1 = *(__half2*)&u.y;
                __half2 h2 = *(__half2*)&u.z, h3 = *(__half2*)&u.w;
                float2 f0 = __half22float2(h0), f1 = __half22float2(h1);
                float2 f2 = __half22float2(h2), f3 = __half22float2(h3);
                acc[0] += vv * f0.x; acc[1] += vv * f0.y;
                acc[2] += vv * f1.x; acc[3] += vv * f1.y;
                acc[4] += vv * f2.x; acc[5] += vv * f2.y;
                acc[6] += vv * f3.x; acc[7] += vv * f3.y;
            }
        }
    }
    #pragma unroll
    for (int i = 0; i < 8; i++) acc[i] += __shfl_xor_sync(0xffffffffu, acc[i], 16);

    // each half-warp writes its 16B slice of the 512B row
    int colbase = sub * 8 + half * 4;
    const float4* xrow = reinterpret_cast<const float4*>(x + (size_t)w * D + colbase);
    float4 xv = __ldg(xrow);
    float a0 = acc[half * 4 + 0], a1 = acc[half * 4 + 1];
    float a2 = acc[half * 4 + 2], a3 = acc[half * 4 + 3];
    reinterpret_cast<float4*>(out + (size_t)w * D + colbase)[0] =
        make_float4(xv.x - 2.f * a0, xv.y - 2.f * a1,
                    xv.z - 2.f * a2, xv.w - 2.f * a3);
}

// ---------------- launch -----------------------------------------------------

extern "C" void kernel_launch(void* const* d_in, const int* in_sizes, int n_in,
                              void* d_out, int out_size) {
    const float* vals = (const float*)d_in[0];
    const float* x    = (const float*)d_in[1];
    const int*   rows = (const int*)d_in[2];
    const int*   cols = (const int*)d_in[3];
    float*       out  = (float*)d_out;

    const int nnz = in_sizes[0];

    float2* dc_ptr;  cudaGetSymbolAddress((void**)&dc_ptr,  g_degcnt);
    int*    cnt_ptr; cudaGetSymbolAddress((void**)&cnt_ptr, g_cntI);
    int*    off_ptr; cudaGetSymbolAddress((void**)&off_ptr, g_off);
    int*    cur_ptr; cudaGetSymbolAddress((void**)&cur_ptr, g_cur);
    int*    bs_ptr;  cudaGetSymbolAddress((void**)&bs_ptr,  g_bsums);

    const int T = 256;

    // 1. zero (deg,count) pairs — 300k float2 = 150k int4
    zero_i4_kernel<<<(N_BOTH * 2 / 4 + T - 1) / T, T>>>((int4*)dc_ptr, N_BOTH * 2 / 4);

    // 2. degrees + histogram (one v2 red per endpoint); x -> fp16; then prep
    deg_hist_kernel<<<(nnz + T - 1) / T, T>>>(vals, rows, cols, nnz);
    {
        int n4 = N_ITEMS * D / 4;
        cvt_x_kernel<<<(n4 + T - 1) / T, T>>>((const float4*)x, n4);
    }
    prep_kernel<<<(N_BOTH + T - 1) / T, T>>>(N_BOTH);

    // 3. exclusive scans: user section, then item section
    {
        int nbU = (N_USERS + SCAN_B - 1) / SCAN_B;
        scan_block_kernel<<<nbU, SCAN_B>>>(cnt_ptr, off_ptr, bs_ptr, N_USERS);
        scan_sums_kernel<<<1, SCAN_B>>>(bs_ptr, nbU);
        scan_add_kernel<<<nbU, SCAN_B>>>(off_ptr, cur_ptr, bs_ptr, N_USERS);
    }
    {
        int nbI = (N_ITEMS + SCAN_B - 1) / SCAN_B;
        scan_block_kernel<<<nbI, SCAN_B>>>(cnt_ptr + N_USERS, off_ptr + N_USERS,
                                           bs_ptr, N_ITEMS);
        scan_sums_kernel<<<1, SCAN_B>>>(bs_ptr, nbI);
        scan_add_kernel<<<nbI, SCAN_B>>>(off_ptr + N_USERS, cur_ptr + N_USERS,
                                         bs_ptr, N_ITEMS);
    }

    // 4. scatter edges into CSR + CSC with fused normalization
    build_kernel<<<(nnz + T - 1) / T, T>>>(vals, rows, cols, nnz);

    // 5. SpMM pass 1: y = A_norm @ x   (fp16 gather, no atomics)
    {
        long long threads = (long long)N_USERS * 32;
        spmm1_kernel<<<(unsigned)((threads + T - 1) / T), T>>>(N_USERS);
    }

    // 6. SpMM pass 2 + finalize: out = x - 2 * (A_norm^T @ y)
    {
        long long threads = (long long)N_ITEMS * 32;
        spmm2_kernel<<<(unsigned)((threads + T - 1) / T), T>>>(x, out, N_ITEMS);
    }
}